// round 1
// baseline (speedup 1.0000x reference)
#include <cuda_runtime.h>
#include <cstdint>

// Problem constants
#define U_NUM   50000
#define I_NUM   20000
#define F_DIM   64
#define N_EDGES 1000000
#define BATCH   131072

#define UF (U_NUM * F_DIM)   // 3,200,000 floats
#define IF (I_NUM * F_DIM)   // 1,280,000 floats

// Scratch: g_U = [U1 | U2 | U3 | gcnU], g_I = [I1 | I2 | I3 | gcnI]
__device__ float g_U[4 * UF];
__device__ float g_I[4 * IF];

// ---------------------------------------------------------------------------
// Zero scratch (U1..U3, I1..I3) and the output scalar
// ---------------------------------------------------------------------------
__global__ void zero_kernel(float* out) {
    size_t i = (size_t)blockIdx.x * blockDim.x + threadIdx.x;
    size_t stride = (size_t)gridDim.x * blockDim.x;
    float4 z = make_float4(0.f, 0.f, 0.f, 0.f);
    float4* pu = reinterpret_cast<float4*>(g_U);
    float4* pi = reinterpret_cast<float4*>(g_I);
    const size_t nu = (size_t)(3 * UF) / 4;
    const size_t ni = (size_t)(3 * IF) / 4;
    for (size_t k = i; k < nu; k += stride) pu[k] = z;
    for (size_t k = i; k < ni; k += stride) pi[k] = z;
    if (i == 0) out[0] = 0.f;
}

// ---------------------------------------------------------------------------
// Vector atomic reduction (sm_90+): 4 floats in one L2 reduction op
// ---------------------------------------------------------------------------
__device__ __forceinline__ void red_add_v4(float* addr, float a, float b, float c, float d) {
    asm volatile("red.global.add.v4.f32 [%0], {%1, %2, %3, %4};"
                 :: "l"(addr), "f"(a), "f"(b), "f"(c), "f"(d)
                 : "memory");
}

// ---------------------------------------------------------------------------
// One propagation stage: both directions per edge.
//   u_dst[row] += ui_val * i_src[col]
//   i_dst[col] += iu_val * u_src[row]
// 16 lanes per edge, float4 per lane (covers F=64).
// ---------------------------------------------------------------------------
__global__ void __launch_bounds__(256) stage_kernel(
    const int*   __restrict__ rows,
    const int*   __restrict__ cols,
    const float* __restrict__ ui_vals,
    const float* __restrict__ iu_vals,
    const float* __restrict__ u_src,
    const float* __restrict__ i_src,
    float* __restrict__ u_dst,
    float* __restrict__ i_dst)
{
    int t = blockIdx.x * blockDim.x + threadIdx.x;
    int e = t >> 4;
    if (e >= N_EDGES) return;
    int g = (t & 15) * 4;

    int   r  = __ldg(rows + e);
    int   c  = __ldg(cols + e);
    float vu = __ldg(ui_vals + e);
    float vi = __ldg(iu_vals + e);

    const float4 iv = *reinterpret_cast<const float4*>(i_src + (size_t)c * F_DIM + g);
    const float4 uv = *reinterpret_cast<const float4*>(u_src + (size_t)r * F_DIM + g);

    red_add_v4(u_dst + (size_t)r * F_DIM + g, vu * iv.x, vu * iv.y, vu * iv.z, vu * iv.w);
    red_add_v4(i_dst + (size_t)c * F_DIM + g, vi * uv.x, vi * uv.y, vi * uv.z, vi * uv.w);
}

// ---------------------------------------------------------------------------
// Layer combine: gcn = e0 + 1/2 e1 + 1/3 e2 + 1/4 e3  (for U and I)
// ---------------------------------------------------------------------------
__global__ void gcn_kernel(const float* __restrict__ u0, const float* __restrict__ i0) {
    const int nu = UF / 4;
    const int ni = IF / 4;
    int idx = blockIdx.x * blockDim.x + threadIdx.x;
    const float c1 = 0.5f, c2 = 1.0f / 3.0f, c3 = 0.25f;

    if (idx < nu) {
        const float4* U1 = reinterpret_cast<const float4*>(g_U);
        const float4* U2 = reinterpret_cast<const float4*>(g_U + UF);
        const float4* U3 = reinterpret_cast<const float4*>(g_U + 2 * UF);
        float4*       GU = reinterpret_cast<float4*>(g_U + 3 * UF);
        float4 a = reinterpret_cast<const float4*>(u0)[idx];
        float4 b = U1[idx], c = U2[idx], d = U3[idx];
        float4 o;
        o.x = a.x + c1 * b.x + c2 * c.x + c3 * d.x;
        o.y = a.y + c1 * b.y + c2 * c.y + c3 * d.y;
        o.z = a.z + c1 * b.z + c2 * c.z + c3 * d.z;
        o.w = a.w + c1 * b.w + c2 * c.w + c3 * d.w;
        GU[idx] = o;
    } else if (idx - nu < ni) {
        int j = idx - nu;
        const float4* I1 = reinterpret_cast<const float4*>(g_I);
        const float4* I2 = reinterpret_cast<const float4*>(g_I + IF);
        const float4* I3 = reinterpret_cast<const float4*>(g_I + 2 * IF);
        float4*       GI = reinterpret_cast<float4*>(g_I + 3 * IF);
        float4 a = reinterpret_cast<const float4*>(i0)[j];
        float4 b = I1[j], c = I2[j], d = I3[j];
        float4 o;
        o.x = a.x + c1 * b.x + c2 * c.x + c3 * d.x;
        o.y = a.y + c1 * b.y + c2 * c.y + c3 * d.y;
        o.z = a.z + c1 * b.z + c2 * c.z + c3 * d.z;
        o.w = a.w + c1 * b.w + c2 * c.w + c3 * d.w;
        GI[idx - nu] = o;
    }
}

// ---------------------------------------------------------------------------
// Contrastive loss for both sides in one kernel. One warp per batch element.
//   si = <old[u], gcn[i]>, sj = <old[u], gcn[j]>
//   contrib = -(si - logaddexp(si, sj)) * degree / num
// ---------------------------------------------------------------------------
__global__ void __launch_bounds__(256) loss_kernel(
    const float* __restrict__ oldU,
    const int*   __restrict__ userU, const int* __restrict__ iiU,
    const int*   __restrict__ ijU,   const float* __restrict__ degU,
    const float* __restrict__ oldI,
    const int*   __restrict__ userI, const int* __restrict__ iiI,
    const int*   __restrict__ ijI,   const float* __restrict__ degI,
    float* __restrict__ out)
{
    const float* gcnU = g_U + 3 * UF;
    const float* gcnI = g_I + 3 * IF;

    int gwid = (blockIdx.x * blockDim.x + threadIdx.x) >> 5;
    int lane = threadIdx.x & 31;
    float contrib = 0.f;

    if (gwid < 2 * BATCH) {
        bool second = gwid >= BATCH;
        int b = second ? gwid - BATCH : gwid;
        const float* oe = second ? oldI : oldU;
        const float* ge = second ? gcnI : gcnU;
        int   iu = second ? __ldg(userI + b) : __ldg(userU + b);
        int   ii = second ? __ldg(iiI + b)   : __ldg(iiU + b);
        int   ij = second ? __ldg(ijI + b)   : __ldg(ijU + b);
        float dg = second ? __ldg(degI + b)  : __ldg(degU + b);

        float2 u  = *reinterpret_cast<const float2*>(oe + (size_t)iu * F_DIM + lane * 2);
        float2 pi = *reinterpret_cast<const float2*>(ge + (size_t)ii * F_DIM + lane * 2);
        float2 pj = *reinterpret_cast<const float2*>(ge + (size_t)ij * F_DIM + lane * 2);

        float si = fmaf(u.x, pi.x, u.y * pi.y);
        float sj = fmaf(u.x, pj.x, u.y * pj.y);
        #pragma unroll
        for (int m = 16; m > 0; m >>= 1) {
            si += __shfl_xor_sync(0xffffffffu, si, m);
            sj += __shfl_xor_sync(0xffffffffu, sj, m);
        }
        // log_ratio = si - logaddexp(si, sj)
        float mx  = fmaxf(si, sj);
        float lae = mx + log1pf(expf(-fabsf(si - sj)));
        float inv = second ? (1.0f / I_NUM) : (1.0f / U_NUM);
        if (lane == 0) contrib = -(si - lae) * dg * inv;
    }

    // Block reduction: 8 warps -> 1 atomicAdd
    __shared__ float sm[8];
    int wib = threadIdx.x >> 5;
    if (lane == 0) sm[wib] = contrib;
    __syncthreads();
    if (threadIdx.x == 0) {
        float s = 0.f;
        #pragma unroll
        for (int w = 0; w < 8; w++) s += sm[w];
        atomicAdd(out, s);
    }
}

// ---------------------------------------------------------------------------
// Launch
// ---------------------------------------------------------------------------
extern "C" void kernel_launch(void* const* d_in, const int* in_sizes, int n_in,
                              void* d_out, int out_size)
{
    // Resolve input ordering: dict order (setup_inputs) vs reference-signature order.
    // dict order:  6 = ui_vals (N_EDGES);  signature order: 6 = degree_U (BATCH)
    bool dict = (in_sizes[6] == N_EDGES);

    const float *embed_user, *embed_item, *old_U, *old_I, *ui_vals, *iu_vals, *degU, *degI;
    const int   *erows, *ecols, *userU, *iiU, *ijU, *userI, *iiI, *ijI;

    if (dict) {
        embed_user = (const float*)d_in[0];
        embed_item = (const float*)d_in[1];
        old_U      = (const float*)d_in[2];
        old_I      = (const float*)d_in[3];
        erows      = (const int*)  d_in[4];
        ecols      = (const int*)  d_in[5];
        ui_vals    = (const float*)d_in[6];
        iu_vals    = (const float*)d_in[7];
        userU      = (const int*)  d_in[8];
        iiU        = (const int*)  d_in[9];
        ijU        = (const int*)  d_in[10];
        degU       = (const float*)d_in[11];
        // d_in[12] = item_z_U (unused)
        userI      = (const int*)  d_in[13];
        iiI        = (const int*)  d_in[14];
        ijI        = (const int*)  d_in[15];
        degI       = (const float*)d_in[16];
        // d_in[17] = item_z_I (unused)
    } else {
        embed_user = (const float*)d_in[0];
        embed_item = (const float*)d_in[1];
        old_U      = (const float*)d_in[2];
        old_I      = (const float*)d_in[3];
        ui_vals    = (const float*)d_in[4];
        iu_vals    = (const float*)d_in[5];
        degU       = (const float*)d_in[6];
        degI       = (const float*)d_in[7];
        erows      = (const int*)  d_in[8];
        ecols      = (const int*)  d_in[9];
        userU      = (const int*)  d_in[10];
        iiU        = (const int*)  d_in[11];
        ijU        = (const int*)  d_in[12];
        // d_in[13] = item_z_U (unused)
        userI      = (const int*)  d_in[14];
        iiI        = (const int*)  d_in[15];
        ijI        = (const int*)  d_in[16];
        // d_in[17] = item_z_I (unused)
        degI       = (const float*)d_in[7];
    }

    float* out = (float*)d_out;

    float* pU = nullptr;
    float* pI = nullptr;
    cudaGetSymbolAddress((void**)&pU, g_U);
    cudaGetSymbolAddress((void**)&pI, g_I);

    float* U1 = pU;            float* I1 = pI;
    float* U2 = pU + UF;       float* I2 = pI + IF;
    float* U3 = pU + 2 * UF;   float* I3 = pI + 2 * IF;

    // 1) zero scratch + output
    zero_kernel<<<2048, 256>>>(out);

    // 2) three propagation stages (both directions fused per stage)
    const int stage_blocks = (N_EDGES * 16 + 255) / 256;
    stage_kernel<<<stage_blocks, 256>>>(erows, ecols, ui_vals, iu_vals,
                                        embed_user, embed_item, U1, I1);
    stage_kernel<<<stage_blocks, 256>>>(erows, ecols, ui_vals, iu_vals,
                                        U1, I1, U2, I2);
    stage_kernel<<<stage_blocks, 256>>>(erows, ecols, ui_vals, iu_vals,
                                        U2, I2, U3, I3);

    // 3) layer combine
    const int gcn_threads = UF / 4 + IF / 4;
    gcn_kernel<<<(gcn_threads + 255) / 256, 256>>>(embed_user, embed_item);

    // 4) both contrastive losses
    const int loss_blocks = (2 * BATCH * 32 + 255) / 256;
    loss_kernel<<<loss_blocks, 256>>>(old_U, userU, iiU, ijU, degU,
                                      old_I, userI, iiI, ijI, degI, out);
}

// round 2
// speedup vs baseline: 1.0607x; 1.0607x over previous
#include <cuda_runtime.h>
#include <cstdint>

// Problem constants
#define U_NUM   50000
#define I_NUM   20000
#define F_DIM   64
#define N_EDGES 1000000
#define BATCH   131072

#define UF (U_NUM * F_DIM)   // 3,200,000 floats
#define IF (I_NUM * F_DIM)   // 1,280,000 floats

// Embedding scratch: g_U = [U1 | U2 | gcnU/U3], g_I = [I1 | I2 | gcnI/I3]
__device__ float g_U[3 * UF];
__device__ float g_I[3 * IF];

// CSR structures (built once per launch, reused for all 3 stages)
__device__ int    g_rowCnt[U_NUM];
__device__ int    g_colCnt[I_NUM];
__device__ int    g_rowOff[U_NUM + 1];
__device__ int    g_colOff[I_NUM + 1];
__device__ int    g_rowCur[U_NUM];
__device__ int    g_colCur[I_NUM];
__device__ float2 g_ui[N_EDGES];   // sorted by row: (.x = col bits, .y = ui_val)
__device__ float2 g_iu[N_EDGES];   // sorted by col: (.x = row bits, .y = iu_val)

// ---------------------------------------------------------------------------
// Zero histogram counters + output scalar
// ---------------------------------------------------------------------------
__global__ void zero_kernel(float* out) {
    int i = blockIdx.x * blockDim.x + threadIdx.x;
    int stride = gridDim.x * blockDim.x;
    for (int k = i; k < U_NUM; k += stride) g_rowCnt[k] = 0;
    for (int k = i; k < I_NUM; k += stride) g_colCnt[k] = 0;
    if (i == 0) out[0] = 0.f;
}

// ---------------------------------------------------------------------------
// Histogram of edge endpoints
// ---------------------------------------------------------------------------
__global__ void __launch_bounds__(256) hist_kernel(
    const int* __restrict__ rows, const int* __restrict__ cols)
{
    int e = blockIdx.x * blockDim.x + threadIdx.x;
    if (e >= N_EDGES) return;
    atomicAdd(&g_rowCnt[__ldg(rows + e)], 1);
    atomicAdd(&g_colCnt[__ldg(cols + e)], 1);
}

// ---------------------------------------------------------------------------
// Exclusive scan of counters -> offsets (+ cursor copies).
// Block 0: rows (U_NUM), block 1: cols (I_NUM). 1024 threads each.
// ---------------------------------------------------------------------------
__global__ void __launch_bounds__(1024) scan_kernel() {
    __shared__ int sm[1024];
    int N; int* cnt; int* off; int* cur;
    if (blockIdx.x == 0) { N = U_NUM; cnt = g_rowCnt; off = g_rowOff; cur = g_rowCur; }
    else                 { N = I_NUM; cnt = g_colCnt; off = g_colOff; cur = g_colCur; }

    const int T = 1024;
    int t = threadIdx.x;
    int chunk = (N + T - 1) / T;
    int lo = t * chunk;
    int hi = lo + chunk; if (hi > N) hi = N; if (lo > N) lo = N;

    int s = 0;
    for (int i = lo; i < hi; i++) s += cnt[i];
    sm[t] = s;
    __syncthreads();

    // Hillis-Steele inclusive scan over 1024 partials
    #pragma unroll
    for (int d = 1; d < T; d <<= 1) {
        int v = (t >= d) ? sm[t - d] : 0;
        __syncthreads();
        sm[t] += v;
        __syncthreads();
    }

    int base = sm[t] - s;   // exclusive prefix of this chunk
    for (int i = lo; i < hi; i++) {
        off[i] = base;
        cur[i] = base;
        base += cnt[i];
    }
    if (t == 0) off[N] = N_EDGES;
}

// ---------------------------------------------------------------------------
// Scatter edges into both sorted lists
// ---------------------------------------------------------------------------
__global__ void __launch_bounds__(256) scatter_kernel(
    const int*   __restrict__ rows, const int* __restrict__ cols,
    const float* __restrict__ ui_vals, const float* __restrict__ iu_vals)
{
    int e = blockIdx.x * blockDim.x + threadIdx.x;
    if (e >= N_EDGES) return;
    int r = __ldg(rows + e);
    int c = __ldg(cols + e);
    int p = atomicAdd(&g_rowCur[r], 1);
    g_ui[p] = make_float2(__int_as_float(c), __ldg(ui_vals + e));
    int q = atomicAdd(&g_colCur[c], 1);
    g_iu[q] = make_float2(__int_as_float(r), __ldg(iu_vals + e));
}

// ---------------------------------------------------------------------------
// CSR SpMM stage: half-warp (16 lanes x float4) per destination node.
// Nodes [0, U_NUM)               : u_dst[n] = sum ui_val * i_src[col]
// Nodes [U_NUM, U_NUM + I_NUM)   : i_dst[n] = sum iu_val * u_src[row]
// If FINAL: instead of writing the layer-3 embedding, write the full
//   gcn = e0 + 1/2 e1 + 1/3 e2 + 1/4 e3 combination (fusing the combine).
// ---------------------------------------------------------------------------
template <bool FINAL>
__global__ void __launch_bounds__(256) spmm_kernel(
    const float* __restrict__ u_src, const float* __restrict__ i_src,
    float* __restrict__ u_dst, float* __restrict__ i_dst,
    const float* __restrict__ u_e0, const float* __restrict__ i_e0,
    const float* __restrict__ u_e1, const float* __restrict__ i_e1,
    const float* __restrict__ u_e2, const float* __restrict__ i_e2)
{
    int hw = (blockIdx.x * blockDim.x + threadIdx.x) >> 4;
    int l4 = (threadIdx.x & 15) * 4;

    const float2* __restrict__ edges;
    const int* off;
    const float* __restrict__ src;
    const float *e0, *e1, *e2;
    float* dst;
    int n;

    if (hw < U_NUM) {
        n = hw; edges = g_ui; off = g_rowOff; src = i_src; dst = u_dst;
        e0 = u_e0; e1 = u_e1; e2 = u_e2;
    } else if (hw < U_NUM + I_NUM) {
        n = hw - U_NUM; edges = g_iu; off = g_colOff; src = u_src; dst = i_dst;
        e0 = i_e0; e1 = i_e1; e2 = i_e2;
    } else {
        return;
    }

    int k   = off[n];
    int end = off[n + 1];
    float4 acc = make_float4(0.f, 0.f, 0.f, 0.f);

    // Unrolled by 2 for memory-level parallelism
    for (; k + 1 < end; k += 2) {
        float2 m0 = __ldg(edges + k);
        float2 m1 = __ldg(edges + k + 1);
        const float4 s0 = __ldg(reinterpret_cast<const float4*>(
            src + ((size_t)__float_as_int(m0.x) << 6) + l4));
        const float4 s1 = __ldg(reinterpret_cast<const float4*>(
            src + ((size_t)__float_as_int(m1.x) << 6) + l4));
        acc.x = fmaf(m0.y, s0.x, fmaf(m1.y, s1.x, acc.x));
        acc.y = fmaf(m0.y, s0.y, fmaf(m1.y, s1.y, acc.y));
        acc.z = fmaf(m0.y, s0.z, fmaf(m1.y, s1.z, acc.z));
        acc.w = fmaf(m0.y, s0.w, fmaf(m1.y, s1.w, acc.w));
    }
    if (k < end) {
        float2 m0 = __ldg(edges + k);
        const float4 s0 = __ldg(reinterpret_cast<const float4*>(
            src + ((size_t)__float_as_int(m0.x) << 6) + l4));
        acc.x = fmaf(m0.y, s0.x, acc.x);
        acc.y = fmaf(m0.y, s0.y, acc.y);
        acc.z = fmaf(m0.y, s0.z, acc.z);
        acc.w = fmaf(m0.y, s0.w, acc.w);
    }

    size_t o = ((size_t)n << 6) + l4;
    if (FINAL) {
        // gcn = e0 + 1/2 e1 + 1/3 e2 + 1/4 e3(acc)
        const float c1 = 0.5f, c2 = 1.0f / 3.0f, c3 = 0.25f;
        float4 a = __ldg(reinterpret_cast<const float4*>(e0 + o));
        float4 b = __ldg(reinterpret_cast<const float4*>(e1 + o));
        float4 c = __ldg(reinterpret_cast<const float4*>(e2 + o));
        float4 g;
        g.x = a.x + c1 * b.x + c2 * c.x + c3 * acc.x;
        g.y = a.y + c1 * b.y + c2 * c.y + c3 * acc.y;
        g.z = a.z + c1 * b.z + c2 * c.z + c3 * acc.z;
        g.w = a.w + c1 * b.w + c2 * c.w + c3 * acc.w;
        *reinterpret_cast<float4*>(dst + o) = g;
    } else {
        *reinterpret_cast<float4*>(dst + o) = acc;
    }
}

// ---------------------------------------------------------------------------
// Contrastive loss for both sides. One warp per batch element.
// ---------------------------------------------------------------------------
__global__ void __launch_bounds__(256) loss_kernel(
    const float* __restrict__ oldU,
    const int*   __restrict__ userU, const int* __restrict__ iiU,
    const int*   __restrict__ ijU,   const float* __restrict__ degU,
    const float* __restrict__ oldI,
    const int*   __restrict__ userI, const int* __restrict__ iiI,
    const int*   __restrict__ ijI,   const float* __restrict__ degI,
    float* __restrict__ out)
{
    const float* gcnU = g_U + 2 * UF;
    const float* gcnI = g_I + 2 * IF;

    int gwid = (blockIdx.x * blockDim.x + threadIdx.x) >> 5;
    int lane = threadIdx.x & 31;
    float contrib = 0.f;

    if (gwid < 2 * BATCH) {
        bool second = gwid >= BATCH;
        int b = second ? gwid - BATCH : gwid;
        const float* oe = second ? oldI : oldU;
        const float* ge = second ? gcnI : gcnU;
        int   iu = second ? __ldg(userI + b) : __ldg(userU + b);
        int   ii = second ? __ldg(iiI + b)   : __ldg(iiU + b);
        int   ij = second ? __ldg(ijI + b)   : __ldg(ijU + b);
        float dg = second ? __ldg(degI + b)  : __ldg(degU + b);

        float2 u  = *reinterpret_cast<const float2*>(oe + (size_t)iu * F_DIM + lane * 2);
        float2 pi = *reinterpret_cast<const float2*>(ge + (size_t)ii * F_DIM + lane * 2);
        float2 pj = *reinterpret_cast<const float2*>(ge + (size_t)ij * F_DIM + lane * 2);

        float si = fmaf(u.x, pi.x, u.y * pi.y);
        float sj = fmaf(u.x, pj.x, u.y * pj.y);
        #pragma unroll
        for (int m = 16; m > 0; m >>= 1) {
            si += __shfl_xor_sync(0xffffffffu, si, m);
            sj += __shfl_xor_sync(0xffffffffu, sj, m);
        }
        float mx  = fmaxf(si, sj);
        float lae = mx + log1pf(expf(-fabsf(si - sj)));
        float inv = second ? (1.0f / I_NUM) : (1.0f / U_NUM);
        if (lane == 0) contrib = -(si - lae) * dg * inv;
    }

    __shared__ float sm[8];
    int wib = threadIdx.x >> 5;
    if (lane == 0) sm[wib] = contrib;
    __syncthreads();
    if (threadIdx.x == 0) {
        float s = 0.f;
        #pragma unroll
        for (int w = 0; w < 8; w++) s += sm[w];
        atomicAdd(out, s);
    }
}

// ---------------------------------------------------------------------------
// Launch
// ---------------------------------------------------------------------------
extern "C" void kernel_launch(void* const* d_in, const int* in_sizes, int n_in,
                              void* d_out, int out_size)
{
    // Resolve input ordering: dict order (setup_inputs) vs reference-signature order.
    bool dict = (in_sizes[6] == N_EDGES);

    const float *embed_user, *embed_item, *old_U, *old_I, *ui_vals, *iu_vals, *degU, *degI;
    const int   *erows, *ecols, *userU, *iiU, *ijU, *userI, *iiI, *ijI;

    if (dict) {
        embed_user = (const float*)d_in[0];
        embed_item = (const float*)d_in[1];
        old_U      = (const float*)d_in[2];
        old_I      = (const float*)d_in[3];
        erows      = (const int*)  d_in[4];
        ecols      = (const int*)  d_in[5];
        ui_vals    = (const float*)d_in[6];
        iu_vals    = (const float*)d_in[7];
        userU      = (const int*)  d_in[8];
        iiU        = (const int*)  d_in[9];
        ijU        = (const int*)  d_in[10];
        degU       = (const float*)d_in[11];
        userI      = (const int*)  d_in[13];
        iiI        = (const int*)  d_in[14];
        ijI        = (const int*)  d_in[15];
        degI       = (const float*)d_in[16];
    } else {
        embed_user = (const float*)d_in[0];
        embed_item = (const float*)d_in[1];
        old_U      = (const float*)d_in[2];
        old_I      = (const float*)d_in[3];
        ui_vals    = (const float*)d_in[4];
        iu_vals    = (const float*)d_in[5];
        degU       = (const float*)d_in[6];
        degI       = (const float*)d_in[7];
        erows      = (const int*)  d_in[8];
        ecols      = (const int*)  d_in[9];
        userU      = (const int*)  d_in[10];
        iiU        = (const int*)  d_in[11];
        ijU        = (const int*)  d_in[12];
        userI      = (const int*)  d_in[14];
        iiI        = (const int*)  d_in[15];
        ijI        = (const int*)  d_in[16];
    }

    float* out = (float*)d_out;

    float* pU = nullptr;
    float* pI = nullptr;
    cudaGetSymbolAddress((void**)&pU, g_U);
    cudaGetSymbolAddress((void**)&pI, g_I);

    float* U1 = pU;          float* I1 = pI;
    float* U2 = pU + UF;     float* I2 = pI + IF;
    float* GU = pU + 2*UF;   float* GI = pI + 2*IF;   // gcn outputs

    const int eblocks = (N_EDGES + 255) / 256;

    // 1) CSR build
    zero_kernel<<<256, 256>>>(out);
    hist_kernel<<<eblocks, 256>>>(erows, ecols);
    scan_kernel<<<2, 1024>>>();
    scatter_kernel<<<eblocks, 256>>>(erows, ecols, ui_vals, iu_vals);

    // 2) three propagation stages (register accumulate, single write per row)
    const int spmm_blocks = ((U_NUM + I_NUM) * 16 + 255) / 256;
    spmm_kernel<false><<<spmm_blocks, 256>>>(embed_user, embed_item, U1, I1,
                                             nullptr, nullptr, nullptr, nullptr,
                                             nullptr, nullptr);
    spmm_kernel<false><<<spmm_blocks, 256>>>(U1, I1, U2, I2,
                                             nullptr, nullptr, nullptr, nullptr,
                                             nullptr, nullptr);
    // stage 3 fused with the layer combine: GU/GI get the final gcn embeddings
    spmm_kernel<true><<<spmm_blocks, 256>>>(U2, I2, GU, GI,
                                            embed_user, embed_item,
                                            U1, I1, U2, I2);

    // 3) both contrastive losses
    const int loss_blocks = (2 * BATCH * 32 + 255) / 256;
    loss_kernel<<<loss_blocks, 256>>>(old_U, userU, iiU, ijU, degU,
                                      old_I, userI, iiI, ijI, degI, out);
}

// round 4
// speedup vs baseline: 1.1214x; 1.0572x over previous
#include <cuda_runtime.h>
#include <cuda_fp16.h>
#include <cstdint>

// Problem constants
#define U_NUM   50000
#define I_NUM   20000
#define F_DIM   64
#define N_EDGES 1000000
#define BATCH   131072

#define UF (U_NUM * F_DIM)   // 3,200,000
#define IF (I_NUM * F_DIM)   // 1,280,000

// Half-precision embedding storage: [eU | U1 | U2 | eI | I1 | I2]
__device__ __half g_h[3 * UF + 3 * IF];
// Final gcn embeddings (fp32 for the loss): [gcnU | gcnI]
__device__ float g_gcn[UF + IF];

// CSR structures
__device__ int    g_rowCnt[U_NUM];
__device__ int    g_colCnt[I_NUM];
__device__ int    g_rowOff[U_NUM + 1];
__device__ int    g_colOff[I_NUM + 1];
__device__ int    g_rowCur[U_NUM];
__device__ int    g_colCur[I_NUM];
__device__ float2 g_ui[N_EDGES];   // sorted by row: (.x = col bits, .y = ui_val)
__device__ float2 g_iu[N_EDGES];   // sorted by col: (.x = row bits, .y = iu_val)

// Offsets into g_h (in halves)
#define OFF_EU  0
#define OFF_U1  (UF)
#define OFF_U2  (2 * UF)
#define OFF_EI  (3 * UF)
#define OFF_I1  (3 * UF + IF)
#define OFF_I2  (3 * UF + 2 * IF)

// ---------------------------------------------------------------------------
// Prep: zero counters + output, convert fp32 embedding tables to half
// ---------------------------------------------------------------------------
__global__ void __launch_bounds__(256) prep_kernel(
    const float* __restrict__ eu, const float* __restrict__ ei, float* out)
{
    int i = blockIdx.x * blockDim.x + threadIdx.x;
    int stride = gridDim.x * blockDim.x;

    uint2* hU = reinterpret_cast<uint2*>(g_h + OFF_EU);
    uint2* hI = reinterpret_cast<uint2*>(g_h + OFF_EI);
    const float4* fu = reinterpret_cast<const float4*>(eu);
    const float4* fi = reinterpret_cast<const float4*>(ei);

    for (int k = i; k < UF / 4; k += stride) {
        float4 v = __ldg(fu + k);
        __half2 h0 = __floats2half2_rn(v.x, v.y);
        __half2 h1 = __floats2half2_rn(v.z, v.w);
        uint2 o; o.x = *reinterpret_cast<unsigned*>(&h0); o.y = *reinterpret_cast<unsigned*>(&h1);
        hU[k] = o;
    }
    for (int k = i; k < IF / 4; k += stride) {
        float4 v = __ldg(fi + k);
        __half2 h0 = __floats2half2_rn(v.x, v.y);
        __half2 h1 = __floats2half2_rn(v.z, v.w);
        uint2 o; o.x = *reinterpret_cast<unsigned*>(&h0); o.y = *reinterpret_cast<unsigned*>(&h1);
        hI[k] = o;
    }
    for (int k = i; k < U_NUM; k += stride) g_rowCnt[k] = 0;
    for (int k = i; k < I_NUM; k += stride) g_colCnt[k] = 0;
    if (i == 0) out[0] = 0.f;
}

// ---------------------------------------------------------------------------
// Histogram: 4 edges per thread, vectorized loads
// ---------------------------------------------------------------------------
__global__ void __launch_bounds__(256) hist_kernel(
    const int* __restrict__ rows, const int* __restrict__ cols)
{
    int q = blockIdx.x * blockDim.x + threadIdx.x;       // quad index
    int base = q * 4;
    if (base >= N_EDGES) return;
    int4 r = __ldg(reinterpret_cast<const int4*>(rows + base));
    int4 c = __ldg(reinterpret_cast<const int4*>(cols + base));
    atomicAdd(&g_rowCnt[r.x], 1); atomicAdd(&g_rowCnt[r.y], 1);
    atomicAdd(&g_rowCnt[r.z], 1); atomicAdd(&g_rowCnt[r.w], 1);
    atomicAdd(&g_colCnt[c.x], 1); atomicAdd(&g_colCnt[c.y], 1);
    atomicAdd(&g_colCnt[c.z], 1); atomicAdd(&g_colCnt[c.w], 1);
}

// ---------------------------------------------------------------------------
// Exclusive scan of counters -> offsets (+ cursors)
// ---------------------------------------------------------------------------
__global__ void __launch_bounds__(1024) scan_kernel() {
    __shared__ int sm[1024];
    int N; int* cnt; int* off; int* cur;
    if (blockIdx.x == 0) { N = U_NUM; cnt = g_rowCnt; off = g_rowOff; cur = g_rowCur; }
    else                 { N = I_NUM; cnt = g_colCnt; off = g_colOff; cur = g_colCur; }

    const int T = 1024;
    int t = threadIdx.x;
    int chunk = (N + T - 1) / T;
    int lo = t * chunk;
    int hi = lo + chunk; if (hi > N) hi = N; if (lo > N) lo = N;

    int s = 0;
    for (int i = lo; i < hi; i++) s += cnt[i];
    sm[t] = s;
    __syncthreads();

    #pragma unroll
    for (int d = 1; d < T; d <<= 1) {
        int v = (t >= d) ? sm[t - d] : 0;
        __syncthreads();
        sm[t] += v;
        __syncthreads();
    }

    int base = sm[t] - s;
    for (int i = lo; i < hi; i++) {
        off[i] = base;
        cur[i] = base;
        base += cnt[i];
    }
    if (t == 0) off[N] = N_EDGES;
}

// ---------------------------------------------------------------------------
// Scatter: 4 edges per thread, independent atomics for MLP
// ---------------------------------------------------------------------------
__global__ void __launch_bounds__(256) scatter_kernel(
    const int*   __restrict__ rows, const int* __restrict__ cols,
    const float* __restrict__ ui_vals, const float* __restrict__ iu_vals)
{
    int q = blockIdx.x * blockDim.x + threadIdx.x;
    int base = q * 4;
    if (base >= N_EDGES) return;
    int4   r  = __ldg(reinterpret_cast<const int4*>(rows + base));
    int4   c  = __ldg(reinterpret_cast<const int4*>(cols + base));
    float4 vu = __ldg(reinterpret_cast<const float4*>(ui_vals + base));
    float4 vi = __ldg(reinterpret_cast<const float4*>(iu_vals + base));

    int p0 = atomicAdd(&g_rowCur[r.x], 1);
    int p1 = atomicAdd(&g_rowCur[r.y], 1);
    int p2 = atomicAdd(&g_rowCur[r.z], 1);
    int p3 = atomicAdd(&g_rowCur[r.w], 1);
    int q0 = atomicAdd(&g_colCur[c.x], 1);
    int q1 = atomicAdd(&g_colCur[c.y], 1);
    int q2 = atomicAdd(&g_colCur[c.z], 1);
    int q3 = atomicAdd(&g_colCur[c.w], 1);

    g_ui[p0] = make_float2(__int_as_float(c.x), vu.x);
    g_ui[p1] = make_float2(__int_as_float(c.y), vu.y);
    g_ui[p2] = make_float2(__int_as_float(c.z), vu.z);
    g_ui[p3] = make_float2(__int_as_float(c.w), vu.w);
    g_iu[q0] = make_float2(__int_as_float(r.x), vi.x);
    g_iu[q1] = make_float2(__int_as_float(r.y), vi.y);
    g_iu[q2] = make_float2(__int_as_float(r.z), vi.z);
    g_iu[q3] = make_float2(__int_as_float(r.w), vi.w);
}

// ---------------------------------------------------------------------------
// CSR SpMM stage. Half-warp (16 lanes x 4 dims) per destination node.
// Sources are half (128B/row), accumulation in fp32.
// FINAL=false : dst is half (next layer input)
// FINAL=true  : dst is fp32 gcn = e0 + 1/2 e1 + 1/3 e2 + 1/4 acc
//              (e0 fp32 input table, e1/e2 are this side's own layer-1/2)
// ---------------------------------------------------------------------------
__device__ __forceinline__ void acc_edge(float4& acc, float w, uint2 raw) {
    __half2 h0 = *reinterpret_cast<__half2*>(&raw.x);
    __half2 h1 = *reinterpret_cast<__half2*>(&raw.y);
    float2 f0 = __half22float2(h0);
    float2 f1 = __half22float2(h1);
    acc.x = fmaf(w, f0.x, acc.x);
    acc.y = fmaf(w, f0.y, acc.y);
    acc.z = fmaf(w, f1.x, acc.z);
    acc.w = fmaf(w, f1.y, acc.w);
}

template <bool FINAL>
__global__ void __launch_bounds__(256) spmm_kernel(
    const __half* __restrict__ u_src, const __half* __restrict__ i_src,
    __half* __restrict__ u_dstH, __half* __restrict__ i_dstH,
    const float* __restrict__ u_e0, const float* __restrict__ i_e0,
    const __half* __restrict__ u_e1, const __half* __restrict__ i_e1,
    const __half* __restrict__ u_e2, const __half* __restrict__ i_e2)
{
    int hw   = (blockIdx.x * blockDim.x + threadIdx.x) >> 4;
    int lane = threadIdx.x & 15;

    const float2* __restrict__ edges;
    const int* off;
    const __half* __restrict__ src;
    const float* e0; const __half* e1; const __half* e2;
    __half* dstH;
    float* dstF;
    int n;

    if (hw < U_NUM) {
        n = hw; edges = g_ui; off = g_rowOff; src = i_src;
        dstH = u_dstH; dstF = g_gcn; e0 = u_e0; e1 = u_e1; e2 = u_e2;
    } else if (hw < U_NUM + I_NUM) {
        n = hw - U_NUM; edges = g_iu; off = g_colOff; src = u_src;
        dstH = i_dstH; dstF = g_gcn + UF; e0 = i_e0; e1 = i_e1; e2 = i_e2;
    } else {
        return;
    }

    int k   = off[n];
    int end = off[n + 1];
    float4 acc = make_float4(0.f, 0.f, 0.f, 0.f);

    for (; k + 3 < end; k += 4) {
        float2 m0 = __ldg(edges + k);
        float2 m1 = __ldg(edges + k + 1);
        float2 m2 = __ldg(edges + k + 2);
        float2 m3 = __ldg(edges + k + 3);
        uint2 r0 = __ldg(reinterpret_cast<const uint2*>(src + ((size_t)__float_as_int(m0.x) << 6)) + lane);
        uint2 r1 = __ldg(reinterpret_cast<const uint2*>(src + ((size_t)__float_as_int(m1.x) << 6)) + lane);
        uint2 r2 = __ldg(reinterpret_cast<const uint2*>(src + ((size_t)__float_as_int(m2.x) << 6)) + lane);
        uint2 r3 = __ldg(reinterpret_cast<const uint2*>(src + ((size_t)__float_as_int(m3.x) << 6)) + lane);
        acc_edge(acc, m0.y, r0);
        acc_edge(acc, m1.y, r1);
        acc_edge(acc, m2.y, r2);
        acc_edge(acc, m3.y, r3);
    }
    for (; k < end; k++) {
        float2 m0 = __ldg(edges + k);
        uint2 r0 = __ldg(reinterpret_cast<const uint2*>(src + ((size_t)__float_as_int(m0.x) << 6)) + lane);
        acc_edge(acc, m0.y, r0);
    }

    size_t o = ((size_t)n << 6) + lane * 4;
    if (FINAL) {
        const float c1 = 0.5f, c2 = 1.0f / 3.0f, c3 = 0.25f;
        float4 a = __ldg(reinterpret_cast<const float4*>(e0 + o));
        uint2 rb = __ldg(reinterpret_cast<const uint2*>(e1 + ((size_t)n << 6)) + lane);
        uint2 rc = __ldg(reinterpret_cast<const uint2*>(e2 + ((size_t)n << 6)) + lane);
        __half2 b0 = *reinterpret_cast<__half2*>(&rb.x);
        __half2 b1 = *reinterpret_cast<__half2*>(&rb.y);
        __half2 cc0 = *reinterpret_cast<__half2*>(&rc.x);
        __half2 cc1 = *reinterpret_cast<__half2*>(&rc.y);
        float2 fb0 = __half22float2(b0), fb1 = __half22float2(b1);
        float2 fc0 = __half22float2(cc0), fc1 = __half22float2(cc1);
        float4 g;
        g.x = a.x + c1 * fb0.x + c2 * fc0.x + c3 * acc.x;
        g.y = a.y + c1 * fb0.y + c2 * fc0.y + c3 * acc.y;
        g.z = a.z + c1 * fb1.x + c2 * fc1.x + c3 * acc.z;
        g.w = a.w + c1 * fb1.y + c2 * fc1.y + c3 * acc.w;
        *reinterpret_cast<float4*>(dstF + o) = g;
    } else {
        __half2 h0 = __floats2half2_rn(acc.x, acc.y);
        __half2 h1 = __floats2half2_rn(acc.z, acc.w);
        uint2 ov; ov.x = *reinterpret_cast<unsigned*>(&h0); ov.y = *reinterpret_cast<unsigned*>(&h1);
        reinterpret_cast<uint2*>(dstH + ((size_t)n << 6))[lane] = ov;
    }
}

// ---------------------------------------------------------------------------
// Contrastive loss for both sides. One warp per batch element.
// ---------------------------------------------------------------------------
__global__ void __launch_bounds__(256) loss_kernel(
    const float* __restrict__ oldU,
    const int*   __restrict__ userU, const int* __restrict__ iiU,
    const int*   __restrict__ ijU,   const float* __restrict__ degU,
    const float* __restrict__ oldI,
    const int*   __restrict__ userI, const int* __restrict__ iiI,
    const int*   __restrict__ ijI,   const float* __restrict__ degI,
    float* __restrict__ out)
{
    const float* gcnU = g_gcn;
    const float* gcnI = g_gcn + UF;

    int gwid = (blockIdx.x * blockDim.x + threadIdx.x) >> 5;
    int lane = threadIdx.x & 31;
    float contrib = 0.f;

    if (gwid < 2 * BATCH) {
        bool second = gwid >= BATCH;
        int b = second ? gwid - BATCH : gwid;
        const float* oe = second ? oldI : oldU;
        const float* ge = second ? gcnI : gcnU;
        int   iu = second ? __ldg(userI + b) : __ldg(userU + b);
        int   ii = second ? __ldg(iiI + b)   : __ldg(iiU + b);
        int   ij = second ? __ldg(ijI + b)   : __ldg(ijU + b);
        float dg = second ? __ldg(degI + b)  : __ldg(degU + b);

        float2 u  = *reinterpret_cast<const float2*>(oe + (size_t)iu * F_DIM + lane * 2);
        float2 pi = *reinterpret_cast<const float2*>(ge + (size_t)ii * F_DIM + lane * 2);
        float2 pj = *reinterpret_cast<const float2*>(ge + (size_t)ij * F_DIM + lane * 2);

        float si = fmaf(u.x, pi.x, u.y * pi.y);
        float sj = fmaf(u.x, pj.x, u.y * pj.y);
        #pragma unroll
        for (int m = 16; m > 0; m >>= 1) {
            si += __shfl_xor_sync(0xffffffffu, si, m);
            sj += __shfl_xor_sync(0xffffffffu, sj, m);
        }
        float mx  = fmaxf(si, sj);
        float lae = mx + log1pf(expf(-fabsf(si - sj)));
        float inv = second ? (1.0f / I_NUM) : (1.0f / U_NUM);
        if (lane == 0) contrib = -(si - lae) * dg * inv;
    }

    __shared__ float sm[8];
    int wib = threadIdx.x >> 5;
    if (lane == 0) sm[wib] = contrib;
    __syncthreads();
    if (threadIdx.x == 0) {
        float s = 0.f;
        #pragma unroll
        for (int w = 0; w < 8; w++) s += sm[w];
        atomicAdd(out, s);
    }
}

// ---------------------------------------------------------------------------
// Launch
// ---------------------------------------------------------------------------
extern "C" void kernel_launch(void* const* d_in, const int* in_sizes, int n_in,
                              void* d_out, int out_size)
{
    bool dict = (in_sizes[6] == N_EDGES);

    const float *embed_user, *embed_item, *old_U, *old_I, *ui_vals, *iu_vals, *degU, *degI;
    const int   *erows, *ecols, *userU, *iiU, *ijU, *userI, *iiI, *ijI;

    if (dict) {
        embed_user = (const float*)d_in[0];
        embed_item = (const float*)d_in[1];
        old_U      = (const float*)d_in[2];
        old_I      = (const float*)d_in[3];
        erows      = (const int*)  d_in[4];
        ecols      = (const int*)  d_in[5];
        ui_vals    = (const float*)d_in[6];
        iu_vals    = (const float*)d_in[7];
        userU      = (const int*)  d_in[8];
        iiU        = (const int*)  d_in[9];
        ijU        = (const int*)  d_in[10];
        degU       = (const float*)d_in[11];
        userI      = (const int*)  d_in[13];
        iiI        = (const int*)  d_in[14];
        ijI        = (const int*)  d_in[15];
        degI       = (const float*)d_in[16];
    } else {
        embed_user = (const float*)d_in[0];
        embed_item = (const float*)d_in[1];
        old_U      = (const float*)d_in[2];
        old_I      = (const float*)d_in[3];
        ui_vals    = (const float*)d_in[4];
        iu_vals    = (const float*)d_in[5];
        degU       = (const float*)d_in[6];
        degI       = (const float*)d_in[7];
        erows      = (const int*)  d_in[8];
        ecols      = (const int*)  d_in[9];
        userU      = (const int*)  d_in[10];
        iiU        = (const int*)  d_in[11];
        ijU        = (const int*)  d_in[12];
        userI      = (const int*)  d_in[14];
        iiI        = (const int*)  d_in[15];
        ijI        = (const int*)  d_in[16];
    }

    float* out = (float*)d_out;

    __half* ph = nullptr;
    cudaGetSymbolAddress((void**)&ph, g_h);
    __half* eU = ph + OFF_EU;  __half* U1 = ph + OFF_U1;  __half* U2 = ph + OFF_U2;
    __half* eI = ph + OFF_EI;  __half* I1 = ph + OFF_I1;  __half* I2 = ph + OFF_I2;

    const int qblocks = (N_EDGES / 4 + 255) / 256;

    // 1) prep + CSR build
    prep_kernel<<<1024, 256>>>(embed_user, embed_item, out);
    hist_kernel<<<qblocks, 256>>>(erows, ecols);
    scan_kernel<<<2, 1024>>>();
    scatter_kernel<<<qblocks, 256>>>(erows, ecols, ui_vals, iu_vals);

    // 2) three propagation stages
    const int spmm_blocks = ((U_NUM + I_NUM) * 16 + 255) / 256;
    spmm_kernel<false><<<spmm_blocks, 256>>>(eU, eI, U1, I1,
                                             nullptr, nullptr, nullptr, nullptr,
                                             nullptr, nullptr);
    spmm_kernel<false><<<spmm_blocks, 256>>>(U1, I1, U2, I2,
                                             nullptr, nullptr, nullptr, nullptr,
                                             nullptr, nullptr);
    // stage 3 fused with layer combine -> g_gcn (fp32); e2 passed EXPLICITLY
    spmm_kernel<true><<<spmm_blocks, 256>>>(U2, I2, nullptr, nullptr,
                                            embed_user, embed_item,
                                            U1, I1, U2, I2);

    // 3) both contrastive losses
    const int loss_blocks = (2 * BATCH * 32 + 255) / 256;
    loss_kernel<<<loss_blocks, 256>>>(old_U, userU, iiU, ijU, degU,
                                      old_I, userI, iiI, ijI, degI, out);
}

// round 5
// speedup vs baseline: 1.1580x; 1.0326x over previous
#include <cuda_runtime.h>
#include <cuda_fp16.h>
#include <cstdint>

// Problem constants
#define U_NUM   50000
#define I_NUM   20000
#define F_DIM   64
#define N_EDGES 1000000
#define BATCH   131072

#define UF (U_NUM * F_DIM)   // 3,200,000
#define IF (I_NUM * F_DIM)   // 1,280,000

// fp16 embedding storage: [eU | U1 | U2 | eI | I1 | I2]
__device__ __half g_h[3 * UF + 3 * IF];
// fp16 copies of the "old" tables for the loss
__device__ __half g_oldU[UF];
__device__ __half g_oldI[IF];
// fp16 final gcn embeddings: [gcnU | gcnI]
__device__ __half g_gcn[UF + IF];

// CSR structures
__device__ int g_rowCnt[U_NUM];
__device__ int g_colCnt[I_NUM];
__device__ int g_rowOff[U_NUM + 1];
__device__ int g_colOff[I_NUM + 1];
__device__ int g_rowCur[U_NUM];
__device__ int g_colCur[I_NUM];
// Packed edges: low 16 bits = index, high 16 bits = fp16 weight
__device__ unsigned g_ui[N_EDGES];   // sorted by row (idx = col, w = ui_val)
__device__ unsigned g_iu[N_EDGES];   // sorted by col (idx = row, w = iu_val)

// Offsets into g_h (in halves)
#define OFF_EU  0
#define OFF_U1  (UF)
#define OFF_U2  (2 * UF)
#define OFF_EI  (3 * UF)
#define OFF_I1  (3 * UF + IF)
#define OFF_I2  (3 * UF + 2 * IF)

__device__ __forceinline__ uint2 f4_to_h4(float4 v) {
    __half2 a = __floats2half2_rn(v.x, v.y);
    __half2 b = __floats2half2_rn(v.z, v.w);
    uint2 o;
    o.x = *reinterpret_cast<unsigned*>(&a);
    o.y = *reinterpret_cast<unsigned*>(&b);
    return o;
}

// ---------------------------------------------------------------------------
// K1: zero counters + output scalar (tiny; must precede hist atomics)
// ---------------------------------------------------------------------------
__global__ void zero_kernel(float* out) {
    int i = blockIdx.x * blockDim.x + threadIdx.x;
    int stride = gridDim.x * blockDim.x;
    for (int k = i; k < U_NUM; k += stride) g_rowCnt[k] = 0;
    for (int k = i; k < I_NUM; k += stride) g_colCnt[k] = 0;
    if (i == 0) out[0] = 0.f;
}

// ---------------------------------------------------------------------------
// K2: fused fp32->fp16 table conversions + endpoint histogram.
// Conversion loops are bandwidth-bound; hist atomics are latency-bound —
// interleaving them keeps the SMs busy during atomic round trips.
// ---------------------------------------------------------------------------
__global__ void __launch_bounds__(256) convhist_kernel(
    const float* __restrict__ eu, const float* __restrict__ ei,
    const float* __restrict__ ou, const float* __restrict__ oi,
    const int*   __restrict__ rows, const int* __restrict__ cols)
{
    int i = blockIdx.x * blockDim.x + threadIdx.x;
    int stride = gridDim.x * blockDim.x;

    // histogram (4 edges / iteration)
    const int4* r4 = reinterpret_cast<const int4*>(rows);
    const int4* c4 = reinterpret_cast<const int4*>(cols);
    for (int q = i; q < N_EDGES / 4; q += stride) {
        int4 r = __ldg(r4 + q);
        int4 c = __ldg(c4 + q);
        atomicAdd(&g_rowCnt[r.x], 1); atomicAdd(&g_rowCnt[r.y], 1);
        atomicAdd(&g_rowCnt[r.z], 1); atomicAdd(&g_rowCnt[r.w], 1);
        atomicAdd(&g_colCnt[c.x], 1); atomicAdd(&g_colCnt[c.y], 1);
        atomicAdd(&g_colCnt[c.z], 1); atomicAdd(&g_colCnt[c.w], 1);
    }

    // conversions
    uint2* hEU = reinterpret_cast<uint2*>(g_h + OFF_EU);
    uint2* hEI = reinterpret_cast<uint2*>(g_h + OFF_EI);
    uint2* hOU = reinterpret_cast<uint2*>(g_oldU);
    uint2* hOI = reinterpret_cast<uint2*>(g_oldI);
    const float4* fu = reinterpret_cast<const float4*>(eu);
    const float4* fi = reinterpret_cast<const float4*>(ei);
    const float4* fo = reinterpret_cast<const float4*>(ou);
    const float4* fp = reinterpret_cast<const float4*>(oi);

    for (int k = i; k < UF / 4; k += stride) hEU[k] = f4_to_h4(__ldg(fu + k));
    for (int k = i; k < IF / 4; k += stride) hEI[k] = f4_to_h4(__ldg(fi + k));
    for (int k = i; k < UF / 4; k += stride) hOU[k] = f4_to_h4(__ldg(fo + k));
    for (int k = i; k < IF / 4; k += stride) hOI[k] = f4_to_h4(__ldg(fp + k));
}

// ---------------------------------------------------------------------------
// K3: exclusive scan of counters -> offsets (+ cursors)
// ---------------------------------------------------------------------------
__global__ void __launch_bounds__(1024) scan_kernel() {
    __shared__ int sm[1024];
    int N; int* cnt; int* off; int* cur;
    if (blockIdx.x == 0) { N = U_NUM; cnt = g_rowCnt; off = g_rowOff; cur = g_rowCur; }
    else                 { N = I_NUM; cnt = g_colCnt; off = g_colOff; cur = g_colCur; }

    const int T = 1024;
    int t = threadIdx.x;
    int chunk = (N + T - 1) / T;
    int lo = t * chunk;
    int hi = lo + chunk; if (hi > N) hi = N; if (lo > N) lo = N;

    int s = 0;
    for (int i = lo; i < hi; i++) s += cnt[i];
    sm[t] = s;
    __syncthreads();

    #pragma unroll
    for (int d = 1; d < T; d <<= 1) {
        int v = (t >= d) ? sm[t - d] : 0;
        __syncthreads();
        sm[t] += v;
        __syncthreads();
    }

    int base = sm[t] - s;
    for (int i = lo; i < hi; i++) {
        off[i] = base;
        cur[i] = base;
        base += cnt[i];
    }
    if (t == 0) off[N] = N_EDGES;
}

// ---------------------------------------------------------------------------
// K4: scatter edges into both sorted lists (4-byte packed entries)
// ---------------------------------------------------------------------------
__device__ __forceinline__ unsigned pack_edge(int idx, float v) {
    __half h = __float2half_rn(v);
    return ((unsigned)__half_as_ushort(h) << 16) | (unsigned)idx;
}

__global__ void __launch_bounds__(256) scatter_kernel(
    const int*   __restrict__ rows, const int* __restrict__ cols,
    const float* __restrict__ ui_vals, const float* __restrict__ iu_vals)
{
    int q = blockIdx.x * blockDim.x + threadIdx.x;
    int base = q * 4;
    if (base >= N_EDGES) return;
    int4   r  = __ldg(reinterpret_cast<const int4*>(rows + base));
    int4   c  = __ldg(reinterpret_cast<const int4*>(cols + base));
    float4 vu = __ldg(reinterpret_cast<const float4*>(ui_vals + base));
    float4 vi = __ldg(reinterpret_cast<const float4*>(iu_vals + base));

    int p0 = atomicAdd(&g_rowCur[r.x], 1);
    int p1 = atomicAdd(&g_rowCur[r.y], 1);
    int p2 = atomicAdd(&g_rowCur[r.z], 1);
    int p3 = atomicAdd(&g_rowCur[r.w], 1);
    int q0 = atomicAdd(&g_colCur[c.x], 1);
    int q1 = atomicAdd(&g_colCur[c.y], 1);
    int q2 = atomicAdd(&g_colCur[c.z], 1);
    int q3 = atomicAdd(&g_colCur[c.w], 1);

    g_ui[p0] = pack_edge(c.x, vu.x);
    g_ui[p1] = pack_edge(c.y, vu.y);
    g_ui[p2] = pack_edge(c.z, vu.z);
    g_ui[p3] = pack_edge(c.w, vu.w);
    g_iu[q0] = pack_edge(r.x, vi.x);
    g_iu[q1] = pack_edge(r.y, vi.y);
    g_iu[q2] = pack_edge(r.z, vi.z);
    g_iu[q3] = pack_edge(r.w, vi.w);
}

// ---------------------------------------------------------------------------
// K5-K7: CSR SpMM stage. Half-warp (16 lanes x 4 dims) per destination node.
// Sources fp16 (128B/row), fp32 accumulation.
// FINAL=false: write fp16 layer output.
// FINAL=true : write fp16 gcn = e0(fp32) + 1/2 e1 + 1/3 e2 + 1/4 acc
// ---------------------------------------------------------------------------
__device__ __forceinline__ void acc_edge(float4& acc, float w, uint2 raw) {
    float2 f0 = __half22float2(*reinterpret_cast<__half2*>(&raw.x));
    float2 f1 = __half22float2(*reinterpret_cast<__half2*>(&raw.y));
    acc.x = fmaf(w, f0.x, acc.x);
    acc.y = fmaf(w, f0.y, acc.y);
    acc.z = fmaf(w, f1.x, acc.z);
    acc.w = fmaf(w, f1.y, acc.w);
}

template <bool FINAL>
__global__ void __launch_bounds__(256) spmm_kernel(
    const __half* __restrict__ u_src, const __half* __restrict__ i_src,
    __half* __restrict__ u_dstH, __half* __restrict__ i_dstH,
    const float* __restrict__ u_e0, const float* __restrict__ i_e0,
    const __half* __restrict__ u_e1, const __half* __restrict__ i_e1,
    const __half* __restrict__ u_e2, const __half* __restrict__ i_e2)
{
    int hw   = (blockIdx.x * blockDim.x + threadIdx.x) >> 4;
    int lane = threadIdx.x & 15;

    const unsigned* __restrict__ edges;
    const int* off;
    const __half* __restrict__ src;
    const float* e0; const __half* e1; const __half* e2;
    __half* dstH;
    __half* gcn;
    int n;

    if (hw < U_NUM) {
        n = hw; edges = g_ui; off = g_rowOff; src = i_src;
        dstH = u_dstH; gcn = g_gcn; e0 = u_e0; e1 = u_e1; e2 = u_e2;
    } else if (hw < U_NUM + I_NUM) {
        n = hw - U_NUM; edges = g_iu; off = g_colOff; src = u_src;
        dstH = i_dstH; gcn = g_gcn + UF; e0 = i_e0; e1 = i_e1; e2 = i_e2;
    } else {
        return;
    }

    int k   = off[n];
    int end = off[n + 1];
    float4 acc = make_float4(0.f, 0.f, 0.f, 0.f);

    for (; k + 3 < end; k += 4) {
        unsigned m0 = __ldg(edges + k);
        unsigned m1 = __ldg(edges + k + 1);
        unsigned m2 = __ldg(edges + k + 2);
        unsigned m3 = __ldg(edges + k + 3);
        uint2 r0 = __ldg(reinterpret_cast<const uint2*>(src + ((m0 & 0xFFFFu) << 6)) + lane);
        uint2 r1 = __ldg(reinterpret_cast<const uint2*>(src + ((m1 & 0xFFFFu) << 6)) + lane);
        uint2 r2 = __ldg(reinterpret_cast<const uint2*>(src + ((m2 & 0xFFFFu) << 6)) + lane);
        uint2 r3 = __ldg(reinterpret_cast<const uint2*>(src + ((m3 & 0xFFFFu) << 6)) + lane);
        acc_edge(acc, __half2float(__ushort_as_half((unsigned short)(m0 >> 16))), r0);
        acc_edge(acc, __half2float(__ushort_as_half((unsigned short)(m1 >> 16))), r1);
        acc_edge(acc, __half2float(__ushort_as_half((unsigned short)(m2 >> 16))), r2);
        acc_edge(acc, __half2float(__ushort_as_half((unsigned short)(m3 >> 16))), r3);
    }
    for (; k < end; k++) {
        unsigned m0 = __ldg(edges + k);
        uint2 r0 = __ldg(reinterpret_cast<const uint2*>(src + ((m0 & 0xFFFFu) << 6)) + lane);
        acc_edge(acc, __half2float(__ushort_as_half((unsigned short)(m0 >> 16))), r0);
    }

    size_t o = ((size_t)n << 6) + lane * 4;
    if (FINAL) {
        const float c1 = 0.5f, c2 = 1.0f / 3.0f, c3 = 0.25f;
        float4 a = __ldg(reinterpret_cast<const float4*>(e0 + o));
        uint2 rb = __ldg(reinterpret_cast<const uint2*>(e1 + ((size_t)n << 6)) + lane);
        uint2 rc = __ldg(reinterpret_cast<const uint2*>(e2 + ((size_t)n << 6)) + lane);
        float2 fb0 = __half22float2(*reinterpret_cast<__half2*>(&rb.x));
        float2 fb1 = __half22float2(*reinterpret_cast<__half2*>(&rb.y));
        float2 fc0 = __half22float2(*reinterpret_cast<__half2*>(&rc.x));
        float2 fc1 = __half22float2(*reinterpret_cast<__half2*>(&rc.y));
        float4 g;
        g.x = a.x + c1 * fb0.x + c2 * fc0.x + c3 * acc.x;
        g.y = a.y + c1 * fb0.y + c2 * fc0.y + c3 * acc.y;
        g.z = a.z + c1 * fb1.x + c2 * fc1.x + c3 * acc.z;
        g.w = a.w + c1 * fb1.y + c2 * fc1.y + c3 * acc.w;
        reinterpret_cast<uint2*>(gcn + ((size_t)n << 6))[lane] = f4_to_h4(g);
    } else {
        reinterpret_cast<uint2*>(dstH + ((size_t)n << 6))[lane] = f4_to_h4(acc);
    }
}

// ---------------------------------------------------------------------------
// K8: contrastive loss for both sides, all-fp16 gathers. Warp per sample.
// ---------------------------------------------------------------------------
__global__ void __launch_bounds__(256) loss_kernel(
    const int*   __restrict__ userU, const int* __restrict__ iiU,
    const int*   __restrict__ ijU,   const float* __restrict__ degU,
    const int*   __restrict__ userI, const int* __restrict__ iiI,
    const int*   __restrict__ ijI,   const float* __restrict__ degI,
    float* __restrict__ out)
{
    int gwid = (blockIdx.x * blockDim.x + threadIdx.x) >> 5;
    int lane = threadIdx.x & 31;
    float contrib = 0.f;

    if (gwid < 2 * BATCH) {
        bool second = gwid >= BATCH;
        int b = second ? gwid - BATCH : gwid;
        const __half* oe = second ? g_oldI : g_oldU;
        const __half* ge = second ? (g_gcn + UF) : g_gcn;
        int   iu = second ? __ldg(userI + b) : __ldg(userU + b);
        int   ii = second ? __ldg(iiI + b)   : __ldg(iiU + b);
        int   ij = second ? __ldg(ijI + b)   : __ldg(ijU + b);
        float dg = second ? __ldg(degI + b)  : __ldg(degU + b);

        unsigned ru = *reinterpret_cast<const unsigned*>(oe + ((size_t)iu << 6) + lane * 2);
        unsigned rp = *reinterpret_cast<const unsigned*>(ge + ((size_t)ii << 6) + lane * 2);
        unsigned rq = *reinterpret_cast<const unsigned*>(ge + ((size_t)ij << 6) + lane * 2);
        float2 u  = __half22float2(*reinterpret_cast<__half2*>(&ru));
        float2 pi = __half22float2(*reinterpret_cast<__half2*>(&rp));
        float2 pj = __half22float2(*reinterpret_cast<__half2*>(&rq));

        float si = fmaf(u.x, pi.x, u.y * pi.y);
        float sj = fmaf(u.x, pj.x, u.y * pj.y);
        #pragma unroll
        for (int m = 16; m > 0; m >>= 1) {
            si += __shfl_xor_sync(0xffffffffu, si, m);
            sj += __shfl_xor_sync(0xffffffffu, sj, m);
        }
        float mx  = fmaxf(si, sj);
        float lae = mx + log1pf(expf(-fabsf(si - sj)));
        float inv = second ? (1.0f / I_NUM) : (1.0f / U_NUM);
        if (lane == 0) contrib = -(si - lae) * dg * inv;
    }

    __shared__ float sm[8];
    int wib = threadIdx.x >> 5;
    if (lane == 0) sm[wib] = contrib;
    __syncthreads();
    if (threadIdx.x == 0) {
        float s = 0.f;
        #pragma unroll
        for (int w = 0; w < 8; w++) s += sm[w];
        atomicAdd(out, s);
    }
}

// ---------------------------------------------------------------------------
// Launch
// ---------------------------------------------------------------------------
extern "C" void kernel_launch(void* const* d_in, const int* in_sizes, int n_in,
                              void* d_out, int out_size)
{
    bool dict = (in_sizes[6] == N_EDGES);

    const float *embed_user, *embed_item, *old_U, *old_I, *ui_vals, *iu_vals, *degU, *degI;
    const int   *erows, *ecols, *userU, *iiU, *ijU, *userI, *iiI, *ijI;

    if (dict) {
        embed_user = (const float*)d_in[0];
        embed_item = (const float*)d_in[1];
        old_U      = (const float*)d_in[2];
        old_I      = (const float*)d_in[3];
        erows      = (const int*)  d_in[4];
        ecols      = (const int*)  d_in[5];
        ui_vals    = (const float*)d_in[6];
        iu_vals    = (const float*)d_in[7];
        userU      = (const int*)  d_in[8];
        iiU        = (const int*)  d_in[9];
        ijU        = (const int*)  d_in[10];
        degU       = (const float*)d_in[11];
        userI      = (const int*)  d_in[13];
        iiI        = (const int*)  d_in[14];
        ijI        = (const int*)  d_in[15];
        degI       = (const float*)d_in[16];
    } else {
        embed_user = (const float*)d_in[0];
        embed_item = (const float*)d_in[1];
        old_U      = (const float*)d_in[2];
        old_I      = (const float*)d_in[3];
        ui_vals    = (const float*)d_in[4];
        iu_vals    = (const float*)d_in[5];
        degU       = (const float*)d_in[6];
        degI       = (const float*)d_in[7];
        erows      = (const int*)  d_in[8];
        ecols      = (const int*)  d_in[9];
        userU      = (const int*)  d_in[10];
        iiU        = (const int*)  d_in[11];
        ijU        = (const int*)  d_in[12];
        userI      = (const int*)  d_in[14];
        iiI        = (const int*)  d_in[15];
        ijI        = (const int*)  d_in[16];
    }

    float* out = (float*)d_out;

    __half* ph = nullptr;
    cudaGetSymbolAddress((void**)&ph, g_h);
    __half* eU = ph + OFF_EU;  __half* U1 = ph + OFF_U1;  __half* U2 = ph + OFF_U2;
    __half* eI = ph + OFF_EI;  __half* I1 = ph + OFF_I1;  __half* I2 = ph + OFF_I2;

    const int qblocks = (N_EDGES / 4 + 255) / 256;

    // 1) zero counters, then fused conversions+histogram, scan, scatter
    zero_kernel<<<128, 256>>>(out);
    convhist_kernel<<<1480, 256>>>(embed_user, embed_item, old_U, old_I, erows, ecols);
    scan_kernel<<<2, 1024>>>();
    scatter_kernel<<<qblocks, 256>>>(erows, ecols, ui_vals, iu_vals);

    // 2) three propagation stages
    const int spmm_blocks = ((U_NUM + I_NUM) * 16 + 255) / 256;
    spmm_kernel<false><<<spmm_blocks, 256>>>(eU, eI, U1, I1,
                                             nullptr, nullptr, nullptr, nullptr,
                                             nullptr, nullptr);
    spmm_kernel<false><<<spmm_blocks, 256>>>(U1, I1, U2, I2,
                                             nullptr, nullptr, nullptr, nullptr,
                                             nullptr, nullptr);
    spmm_kernel<true><<<spmm_blocks, 256>>>(U2, I2, nullptr, nullptr,
                                            embed_user, embed_item,
                                            U1, I1, U2, I2);

    // 3) both contrastive losses (all-fp16 gathers)
    const int loss_blocks = (2 * BATCH * 32 + 255) / 256;
    loss_kernel<<<loss_blocks, 256>>>(userU, iiU, ijU, degU,
                                      userI, iiI, ijI, degI, out);
}

// round 6
// speedup vs baseline: 1.3911x; 1.2013x over previous
#include <cuda_runtime.h>
#include <cuda_fp16.h>
#include <cstdint>

// Problem constants
#define U_NUM   50000
#define I_NUM   20000
#define NTOT    (U_NUM + I_NUM)
#define F_DIM   64
#define N_EDGES 1000000
#define BATCH   131072

#define UF (U_NUM * F_DIM)
#define IF (I_NUM * F_DIM)

// fp16 embedding storage: [eU | U1 | U2 | eI | I1 | I2]
__device__ __half g_h[3 * UF + 3 * IF];
// fp16 final gcn embeddings: [gcnU | gcnI]
__device__ __half g_gcn[UF + IF];

// Unified CSR: counters/offsets over U rows (0..U_NUM) then I cols (U_NUM..NTOT)
__device__ int g_cnt[NTOT];
__device__ int g_off[NTOT + 1];
__device__ int g_cur[NTOT];
__device__ int g_blockSum[1024];
__device__ int g_blockBase[1024];
// Packed edges: low 16 = index, high 16 = fp16 weight.
// [0, N_EDGES) row-sorted (idx=col, w=ui), [N_EDGES, 2N) col-sorted (idx=row, w=iu)
__device__ unsigned g_edges[2 * N_EDGES];

// Software grid barrier state (self-resetting; sense is monotonic across replays)
__device__ unsigned g_barCnt = 0;
__device__ unsigned g_barSense = 0;

#define OFF_EU  0
#define OFF_U1  (UF)
#define OFF_U2  (2 * UF)
#define OFF_EI  (3 * UF)
#define OFF_I1  (3 * UF + IF)
#define OFF_I2  (3 * UF + 2 * IF)

__device__ __forceinline__ void gbar(unsigned nb) {
    __syncthreads();
    if (threadIdx.x == 0) {
        __threadfence();
        volatile unsigned* sp = &g_barSense;
        unsigned gen = *sp;
        if (atomicAdd(&g_barCnt, 1) == nb - 1) {
            atomicExch(&g_barCnt, 0);
            __threadfence();
            *sp = gen + 1;
        } else {
            while (*sp == gen) __nanosleep(64);
        }
        __threadfence();
    }
    __syncthreads();
}

__device__ __forceinline__ uint2 f4_to_h4(float4 v) {
    __half2 a = __floats2half2_rn(v.x, v.y);
    __half2 b = __floats2half2_rn(v.z, v.w);
    uint2 o;
    o.x = *reinterpret_cast<unsigned*>(&a);
    o.y = *reinterpret_cast<unsigned*>(&b);
    return o;
}

__device__ __forceinline__ unsigned pack_edge(int idx, float v) {
    __half h = __float2half_rn(v);
    return ((unsigned)__half_as_ushort(h) << 16) | (unsigned)idx;
}

__device__ __forceinline__ void acc_edge(float4& acc, unsigned m, uint2 raw) {
    float w = __half2float(__ushort_as_half((unsigned short)(m >> 16)));
    float2 f0 = __half22float2(*reinterpret_cast<__half2*>(&raw.x));
    float2 f1 = __half22float2(*reinterpret_cast<__half2*>(&raw.y));
    acc.x = fmaf(w, f0.x, acc.x);
    acc.y = fmaf(w, f0.y, acc.y);
    acc.z = fmaf(w, f1.x, acc.z);
    acc.w = fmaf(w, f1.y, acc.w);
}

// One SpMM pass over all 70K destination nodes, half-warp per node, grid-stride.
// uSrc/iSrc are the gather tables (fp16). Returns accumulation in caller-provided
// writeback lambda style via template flag.
template <bool FINAL>
__device__ void spmm_phase(
    const __half* __restrict__ uSrc, const __half* __restrict__ iSrc,
    __half* __restrict__ uDst, __half* __restrict__ iDst,
    const float* __restrict__ uE0, const float* __restrict__ iE0,
    const __half* __restrict__ uE1, const __half* __restrict__ iE1,
    int nb)
{
    int lane = threadIdx.x & 15;
    int hw0  = (blockIdx.x * 256 + threadIdx.x) >> 4;
    int nHW  = nb * 16;

    for (int n = hw0; n < NTOT; n += nHW) {
        const __half* src;
        __half* dstRow;
        const float* e0 = nullptr; const __half* e1 = nullptr; const __half* e2 = nullptr;
        __half* gcnRow = nullptr;
        int local;
        if (n < U_NUM) {
            local = n; src = iSrc;
            dstRow = uDst + ((size_t)local << 6);
            if (FINAL) { e0 = uE0; e1 = uE1; e2 = uSrc; gcnRow = g_gcn + ((size_t)local << 6); }
        } else {
            local = n - U_NUM; src = uSrc;
            dstRow = iDst + ((size_t)local << 6);
            if (FINAL) { e0 = iE0; e1 = iE1; e2 = iSrc; gcnRow = g_gcn + UF + ((size_t)local << 6); }
        }

        int k   = __ldg(g_off + n);
        int end = __ldg(g_off + n + 1);
        float4 acc = make_float4(0.f, 0.f, 0.f, 0.f);

        for (; k + 3 < end; k += 4) {
            unsigned m0 = __ldg(g_edges + k);
            unsigned m1 = __ldg(g_edges + k + 1);
            unsigned m2 = __ldg(g_edges + k + 2);
            unsigned m3 = __ldg(g_edges + k + 3);
            uint2 r0 = __ldg(reinterpret_cast<const uint2*>(src + ((size_t)(m0 & 0xFFFFu) << 6)) + lane);
            uint2 r1 = __ldg(reinterpret_cast<const uint2*>(src + ((size_t)(m1 & 0xFFFFu) << 6)) + lane);
            uint2 r2 = __ldg(reinterpret_cast<const uint2*>(src + ((size_t)(m2 & 0xFFFFu) << 6)) + lane);
            uint2 r3 = __ldg(reinterpret_cast<const uint2*>(src + ((size_t)(m3 & 0xFFFFu) << 6)) + lane);
            acc_edge(acc, m0, r0);
            acc_edge(acc, m1, r1);
            acc_edge(acc, m2, r2);
            acc_edge(acc, m3, r3);
        }
        for (; k < end; k++) {
            unsigned m0 = __ldg(g_edges + k);
            uint2 r0 = __ldg(reinterpret_cast<const uint2*>(src + ((size_t)(m0 & 0xFFFFu) << 6)) + lane);
            acc_edge(acc, m0, r0);
        }

        if (FINAL) {
            const float c1 = 0.5f, c2 = 1.0f / 3.0f, c3 = 0.25f;
            float4 a = __ldg(reinterpret_cast<const float4*>(e0 + ((size_t)local << 6)) + lane);
            uint2 rb = __ldg(reinterpret_cast<const uint2*>(e1 + ((size_t)local << 6)) + lane);
            uint2 rc = __ldg(reinterpret_cast<const uint2*>(e2 + ((size_t)local << 6)) + lane);
            float2 fb0 = __half22float2(*reinterpret_cast<__half2*>(&rb.x));
            float2 fb1 = __half22float2(*reinterpret_cast<__half2*>(&rb.y));
            float2 fc0 = __half22float2(*reinterpret_cast<__half2*>(&rc.x));
            float2 fc1 = __half22float2(*reinterpret_cast<__half2*>(&rc.y));
            float4 g;
            g.x = a.x + c1 * fb0.x + c2 * fc0.x + c3 * acc.x;
            g.y = a.y + c1 * fb0.y + c2 * fc0.y + c3 * acc.y;
            g.z = a.z + c1 * fb1.x + c2 * fc1.x + c3 * acc.z;
            g.w = a.w + c1 * fb1.y + c2 * fc1.y + c3 * acc.w;
            reinterpret_cast<uint2*>(gcnRow)[lane] = f4_to_h4(g);
        } else {
            reinterpret_cast<uint2*>(dstRow)[lane] = f4_to_h4(acc);
        }
    }
}

// ---------------------------------------------------------------------------
// The single fused persistent kernel
// ---------------------------------------------------------------------------
__global__ void __launch_bounds__(256, 4) fused_kernel(
    const float* __restrict__ eu, const float* __restrict__ ei,
    const float* __restrict__ oldU, const float* __restrict__ oldI,
    const int*   __restrict__ rows, const int* __restrict__ cols,
    const float* __restrict__ ui_vals, const float* __restrict__ iu_vals,
    const int* __restrict__ userU, const int* __restrict__ iiU,
    const int* __restrict__ ijU,   const float* __restrict__ degU,
    const int* __restrict__ userI, const int* __restrict__ iiI,
    const int* __restrict__ ijI,   const float* __restrict__ degI,
    float* __restrict__ out)
{
    __shared__ int   s_buf[1024];
    __shared__ int   s_redi[8];
    __shared__ float s_redf[8];

    const int nb   = gridDim.x;
    const int b    = blockIdx.x;
    const int tid  = threadIdx.x;
    const int gtid = b * 256 + tid;
    const int gsz  = nb * 256;
    const int lane = tid & 31;
    const int wib  = tid >> 5;

    __half* eU = g_h + OFF_EU;  __half* U1 = g_h + OFF_U1;  __half* U2 = g_h + OFF_U2;
    __half* eI = g_h + OFF_EI;  __half* I1 = g_h + OFF_I1;  __half* I2 = g_h + OFF_I2;

    // ---- Phase 0: zero counters + out, convert tables to fp16 ----
    {
        uint2* hEU = reinterpret_cast<uint2*>(eU);
        uint2* hEI = reinterpret_cast<uint2*>(eI);
        const float4* fu = reinterpret_cast<const float4*>(eu);
        const float4* fi = reinterpret_cast<const float4*>(ei);
        for (int k = gtid; k < UF / 4; k += gsz) hEU[k] = f4_to_h4(__ldg(fu + k));
        for (int k = gtid; k < IF / 4; k += gsz) hEI[k] = f4_to_h4(__ldg(fi + k));
        for (int k = gtid; k < NTOT; k += gsz) g_cnt[k] = 0;
        if (gtid == 0) out[0] = 0.f;
    }
    gbar(nb);

    // ---- Phase 1: histogram ----
    {
        const int4* r4 = reinterpret_cast<const int4*>(rows);
        const int4* c4 = reinterpret_cast<const int4*>(cols);
        for (int q = gtid; q < N_EDGES / 4; q += gsz) {
            int4 r = __ldg(r4 + q);
            int4 c = __ldg(c4 + q);
            atomicAdd(&g_cnt[r.x], 1); atomicAdd(&g_cnt[r.y], 1);
            atomicAdd(&g_cnt[r.z], 1); atomicAdd(&g_cnt[r.w], 1);
            atomicAdd(&g_cnt[U_NUM + c.x], 1); atomicAdd(&g_cnt[U_NUM + c.y], 1);
            atomicAdd(&g_cnt[U_NUM + c.z], 1); atomicAdd(&g_cnt[U_NUM + c.w], 1);
        }
    }
    gbar(nb);

    // ---- Phase 2: per-block chunk sums ----
    const int chunk = (NTOT + nb - 1) / nb;
    const int lo = b * chunk;
    const int hi = (lo + chunk < NTOT) ? lo + chunk : NTOT;
    {
        int s = 0;
        for (int i = lo + tid; i < hi; i += 256) s += __ldcg(g_cnt + i);
        #pragma unroll
        for (int m = 16; m > 0; m >>= 1) s += __shfl_xor_sync(0xffffffffu, s, m);
        if (lane == 0) s_redi[wib] = s;
        __syncthreads();
        if (tid == 0) {
            int t = 0;
            #pragma unroll
            for (int w = 0; w < 8; w++) t += s_redi[w];
            g_blockSum[b] = t;
        }
    }
    gbar(nb);

    // ---- Phase 3: block 0 exclusive-scans the block sums ----
    if (b == 0) {
        for (int i = tid; i < nb; i += 256) s_buf[i] = __ldcg(g_blockSum + i);
        __syncthreads();
        if (tid < 32) {
            int carry = 0;
            for (int base = 0; base < nb; base += 32) {
                int v = (base + tid < nb) ? s_buf[base + tid] : 0;
                int orig = v;
                #pragma unroll
                for (int d = 1; d < 32; d <<= 1) {
                    int t = __shfl_up_sync(0xffffffffu, v, d);
                    if (tid >= d) v += t;
                }
                if (base + tid < nb) s_buf[base + tid] = carry + v - orig;
                carry += __shfl_sync(0xffffffffu, v, 31);
            }
        }
        __syncthreads();
        for (int i = tid; i < nb; i += 256) g_blockBase[i] = s_buf[i];
    }
    gbar(nb);

    // ---- Phase 4: local exclusive prefix within chunk -> off/cur ----
    {
        int cntL = hi - lo;
        for (int i = tid; i < cntL; i += 256) s_buf[i] = __ldcg(g_cnt + lo + i);
        __syncthreads();
        if (tid < 32 && cntL > 0) {
            int carry = 0;
            for (int base = 0; base < cntL; base += 32) {
                int v = (base + tid < cntL) ? s_buf[base + tid] : 0;
                int orig = v;
                #pragma unroll
                for (int d = 1; d < 32; d <<= 1) {
                    int t = __shfl_up_sync(0xffffffffu, v, d);
                    if (tid >= d) v += t;
                }
                if (base + tid < cntL) s_buf[base + tid] = carry + v - orig;
                carry += __shfl_sync(0xffffffffu, v, 31);
            }
        }
        __syncthreads();
        int basep = (cntL > 0) ? __ldcg(g_blockBase + b) : 0;
        for (int i = tid; i < cntL; i += 256) {
            int o = basep + s_buf[i];
            g_off[lo + i] = o;
            g_cur[lo + i] = o;
        }
        if (gtid == 0) g_off[NTOT] = 2 * N_EDGES;
    }
    gbar(nb);

    // ---- Phase 5: scatter edges ----
    {
        const int4*   r4 = reinterpret_cast<const int4*>(rows);
        const int4*   c4 = reinterpret_cast<const int4*>(cols);
        const float4* u4 = reinterpret_cast<const float4*>(ui_vals);
        const float4* i4 = reinterpret_cast<const float4*>(iu_vals);
        for (int q = gtid; q < N_EDGES / 4; q += gsz) {
            int4   r  = __ldg(r4 + q);
            int4   c  = __ldg(c4 + q);
            float4 vu = __ldg(u4 + q);
            float4 vi = __ldg(i4 + q);
            int p0 = atomicAdd(&g_cur[r.x], 1);
            int p1 = atomicAdd(&g_cur[r.y], 1);
            int p2 = atomicAdd(&g_cur[r.z], 1);
            int p3 = atomicAdd(&g_cur[r.w], 1);
            int q0 = atomicAdd(&g_cur[U_NUM + c.x], 1);
            int q1 = atomicAdd(&g_cur[U_NUM + c.y], 1);
            int q2 = atomicAdd(&g_cur[U_NUM + c.z], 1);
            int q3 = atomicAdd(&g_cur[U_NUM + c.w], 1);
            g_edges[p0] = pack_edge(c.x, vu.x);
            g_edges[p1] = pack_edge(c.y, vu.y);
            g_edges[p2] = pack_edge(c.z, vu.z);
            g_edges[p3] = pack_edge(c.w, vu.w);
            g_edges[q0] = pack_edge(r.x, vi.x);
            g_edges[q1] = pack_edge(r.y, vi.y);
            g_edges[q2] = pack_edge(r.z, vi.z);
            g_edges[q3] = pack_edge(r.w, vi.w);
        }
    }
    gbar(nb);

    // ---- Phases 6-8: propagation ----
    spmm_phase<false>(eU, eI, U1, I1, nullptr, nullptr, nullptr, nullptr, nb);
    gbar(nb);
    spmm_phase<false>(U1, I1, U2, I2, nullptr, nullptr, nullptr, nullptr, nb);
    gbar(nb);
    spmm_phase<true>(U2, I2, nullptr, nullptr, eu, ei, U1, I1, nb);
    gbar(nb);

    // ---- Phase 9: contrastive losses ----
    {
        int wg = gtid >> 5;
        int nW = nb * 8;
        float bsum = 0.f;
        for (int s = wg; s < 2 * BATCH; s += nW) {
            bool second = s >= BATCH;
            int bb = second ? s - BATCH : s;
            const float*  oe = second ? oldI : oldU;
            const __half* ge = second ? (g_gcn + UF) : g_gcn;
            int   iu = second ? __ldg(userI + bb) : __ldg(userU + bb);
            int   ii = second ? __ldg(iiI + bb)   : __ldg(iiU + bb);
            int   ij = second ? __ldg(ijI + bb)   : __ldg(ijU + bb);
            float dg = second ? __ldg(degI + bb)  : __ldg(degU + bb);

            float2 u = __ldg(reinterpret_cast<const float2*>(oe + ((size_t)iu << 6)) + lane);
            unsigned rp = *reinterpret_cast<const unsigned*>(ge + ((size_t)ii << 6) + lane * 2);
            unsigned rq = *reinterpret_cast<const unsigned*>(ge + ((size_t)ij << 6) + lane * 2);
            float2 pi = __half22float2(*reinterpret_cast<__half2*>(&rp));
            float2 pj = __half22float2(*reinterpret_cast<__half2*>(&rq));

            float si = fmaf(u.x, pi.x, u.y * pi.y);
            float sj = fmaf(u.x, pj.x, u.y * pj.y);
            #pragma unroll
            for (int m = 16; m > 0; m >>= 1) {
                si += __shfl_xor_sync(0xffffffffu, si, m);
                sj += __shfl_xor_sync(0xffffffffu, sj, m);
            }
            float mx  = fmaxf(si, sj);
            float lae = mx + log1pf(expf(-fabsf(si - sj)));
            float inv = second ? (1.0f / I_NUM) : (1.0f / U_NUM);
            if (lane == 0) bsum += -(si - lae) * dg * inv;
        }
        if (lane == 0) s_redf[wib] = bsum;
        __syncthreads();
        if (tid == 0) {
            float s = 0.f;
            #pragma unroll
            for (int w = 0; w < 8; w++) s += s_redf[w];
            atomicAdd(out, s);
        }
    }
}

// ---------------------------------------------------------------------------
// Launch
// ---------------------------------------------------------------------------
extern "C" void kernel_launch(void* const* d_in, const int* in_sizes, int n_in,
                              void* d_out, int out_size)
{
    bool dict = (in_sizes[6] == N_EDGES);

    const float *embed_user, *embed_item, *old_U, *old_I, *ui_vals, *iu_vals, *degU, *degI;
    const int   *erows, *ecols, *userU, *iiU, *ijU, *userI, *iiI, *ijI;

    if (dict) {
        embed_user = (const float*)d_in[0];
        embed_item = (const float*)d_in[1];
        old_U      = (const float*)d_in[2];
        old_I      = (const float*)d_in[3];
        erows      = (const int*)  d_in[4];
        ecols      = (const int*)  d_in[5];
        ui_vals    = (const float*)d_in[6];
        iu_vals    = (const float*)d_in[7];
        userU      = (const int*)  d_in[8];
        iiU        = (const int*)  d_in[9];
        ijU        = (const int*)  d_in[10];
        degU       = (const float*)d_in[11];
        userI      = (const int*)  d_in[13];
        iiI        = (const int*)  d_in[14];
        ijI        = (const int*)  d_in[15];
        degI       = (const float*)d_in[16];
    } else {
        embed_user = (const float*)d_in[0];
        embed_item = (const float*)d_in[1];
        old_U      = (const float*)d_in[2];
        old_I      = (const float*)d_in[3];
        ui_vals    = (const float*)d_in[4];
        iu_vals    = (const float*)d_in[5];
        degU       = (const float*)d_in[6];
        degI       = (const float*)d_in[7];
        erows      = (const int*)  d_in[8];
        ecols      = (const int*)  d_in[9];
        userU      = (const int*)  d_in[10];
        iiU        = (const int*)  d_in[11];
        ijU        = (const int*)  d_in[12];
        userI      = (const int*)  d_in[14];
        iiI        = (const int*)  d_in[15];
        ijI        = (const int*)  d_in[16];
    }

    float* out = (float*)d_out;

    int dev = 0;
    cudaGetDevice(&dev);
    int sms = 0;
    cudaDeviceGetAttribute(&sms, cudaDevAttrMultiProcessorCount, dev);
    int nb = sms * 4;            // co-resident with __launch_bounds__(256, 4)
    if (nb > 1024) nb = 1024;

    fused_kernel<<<nb, 256>>>(embed_user, embed_item, old_U, old_I,
                              erows, ecols, ui_vals, iu_vals,
                              userU, iiU, ijU, degU,
                              userI, iiI, ijI, degI, out);
}